// round 6
// baseline (speedup 1.0000x reference)
#include <cuda_runtime.h>

// out[row] = sum_l in[row*1024 + l] / (l+1),  rows = 131072, L = 1024.
//
// R6: persistent blocks + warp-level dynamic work queue.
// Static row splits convert per-SM speed variance (near/far L2 die: 234 vs
// 262 cyc) into a DRAM-idle tail (~19% idle in R3/R5). Warps now grab 8-row
// chunks via atomicAdd on a global counter, so fast SMs take more work and
// the tail shrinks to one chunk. Weights in smem, __ldcs streaming loads,
// 8 front-batched float4 per row, shfl-tree reduce.

static constexpr int L       = 1024;
static constexpr int ROWS    = 4 * 8 * 4096;   // 131072
static constexpr int THREADS = 256;            // 8 warps
static constexpr int GRID    = 152 * 5;        // one resident wave
static constexpr int RPG     = 8;              // rows per grab (ROWS % RPG == 0)

__device__ int g_row_counter;

__global__ void reset_counter_kernel() {
    g_row_counter = 0;
}

__global__ __launch_bounds__(THREADS, 5)
void fractal_dim_kernel(const float* __restrict__ in, float* __restrict__ out) {
    __shared__ float4 w4[L / 4];   // w4[i] = {1/(4i+1), ..., 1/(4i+4)}

    const int t = threadIdx.x;
    {
        int base = t * 4;
        float4 w;
        w.x = 1.0f / (float)(base + 1);
        w.y = 1.0f / (float)(base + 2);
        w.z = 1.0f / (float)(base + 3);
        w.w = 1.0f / (float)(base + 4);
        w4[t] = w;
    }
    __syncthreads();

    const int lane = t & 31;

    for (;;) {
        // Warp-collective grab of RPG rows.
        int base_row;
        if (lane == 0) {
            base_row = atomicAdd(&g_row_counter, RPG);
        }
        base_row = __shfl_sync(0xffffffffu, base_row, 0);
        if (base_row >= ROWS) break;

        #pragma unroll
        for (int rr = 0; rr < RPG; rr++) {
            const int row = base_row + rr;
            const float4* p = reinterpret_cast<const float4*>(in + (size_t)row * L) + lane;

            // Front-batch 8 loads (MLP=8 per warp), read-once streaming.
            float4 v[8];
            #pragma unroll
            for (int k = 0; k < 8; k++) {
                v[k] = __ldcs(p + k * 32);   // warp stride = 32 float4 = 128 floats
            }

            float s0 = 0.0f, s1 = 0.0f;
            #pragma unroll
            for (int k = 0; k < 8; k++) {
                float4 w = w4[lane + 32 * k];
                s0 = fmaf(v[k].x, w.x, s0);
                s1 = fmaf(v[k].y, w.y, s1);
                s0 = fmaf(v[k].z, w.z, s0);
                s1 = fmaf(v[k].w, w.w, s1);
            }
            float s = s0 + s1;

            #pragma unroll
            for (int off = 16; off > 0; off >>= 1) {
                s += __shfl_xor_sync(0xffffffffu, s, off);
            }

            if (lane == 0) {
                out[row] = s;
            }
        }
    }
}

extern "C" void kernel_launch(void* const* d_in, const int* in_sizes, int n_in,
                              void* d_out, int out_size) {
    const float* in  = (const float*)d_in[0];
    float*       out = (float*)d_out;

    reset_counter_kernel<<<1, 1>>>();
    fractal_dim_kernel<<<GRID, THREADS>>>(in, out);
}

// round 7
// speedup vs baseline: 1.0426x; 1.0426x over previous
#include <cuda_runtime.h>

// out[row] = sum_l in[row*1024 + l] / (l+1),  rows = 131072, L = 1024.
//
// R7: hybrid scheduling.
//  - Bulk (115520 rows = 6080 warps * 19 rows): static, atomic-free, identical
//    to the proven R5 loop.
//  - Tail (15552 rows): warp-level dynamic queue, chunk=4, with the NEXT grab's
//    atomicAdd issued before processing the CURRENT chunk (latency hidden).
//    R6 regressed because every grab's 318-cyc round-trip stalled the warp.
//  - Counter self-resets via a blocks-done counter inside the kernel: no extra
//    graph node (R6's reset kernel cost ~4us of graph time).

static constexpr int L        = 1024;
static constexpr int ROWS     = 4 * 8 * 4096;    // 131072
static constexpr int THREADS  = 256;             // 8 warps
static constexpr int GRID     = 152 * 5;         // one resident wave
static constexpr int WARPS    = GRID * (THREADS / 32);      // 6080
static constexpr int SRPW     = 19;                          // static rows/warp
static constexpr int SROWS    = WARPS * SRPW;                // 115520
static constexpr int RPG      = 4;               // dynamic rows per grab; (ROWS-SROWS)%RPG==0

__device__ int g_ctr;    // dynamic row counter (offset past SROWS)
__device__ int g_done;   // blocks finished

__device__ __forceinline__ void process_row(const float* __restrict__ in,
                                            float* __restrict__ out,
                                            const float4* __restrict__ w4,
                                            int lane, int row) {
    const float4* p = reinterpret_cast<const float4*>(in + (size_t)row * L) + lane;

    // Front-batch 8 loads (MLP=8 per warp), read-once streaming.
    float4 v[8];
    #pragma unroll
    for (int k = 0; k < 8; k++) {
        v[k] = __ldcs(p + k * 32);   // warp stride = 32 float4 = 128 floats
    }

    float s0 = 0.0f, s1 = 0.0f;
    #pragma unroll
    for (int k = 0; k < 8; k++) {
        float4 w = w4[lane + 32 * k];
        s0 = fmaf(v[k].x, w.x, s0);
        s1 = fmaf(v[k].y, w.y, s1);
        s0 = fmaf(v[k].z, w.z, s0);
        s1 = fmaf(v[k].w, w.w, s1);
    }
    float s = s0 + s1;

    #pragma unroll
    for (int off = 16; off > 0; off >>= 1) {
        s += __shfl_xor_sync(0xffffffffu, s, off);
    }

    if (lane == 0) {
        out[row] = s;
    }
}

__global__ __launch_bounds__(THREADS, 5)
void fractal_dim_kernel(const float* __restrict__ in, float* __restrict__ out) {
    __shared__ float4 w4[L / 4];   // w4[i] = {1/(4i+1), ..., 1/(4i+4)}

    const int t = threadIdx.x;
    {
        int base = t * 4;
        float4 w;
        w.x = 1.0f / (float)(base + 1);
        w.y = 1.0f / (float)(base + 2);
        w.z = 1.0f / (float)(base + 3);
        w.w = 1.0f / (float)(base + 4);
        w4[t] = w;
    }
    __syncthreads();

    const int lane = t & 31;
    const int wid  = t >> 5;
    const int wg   = blockIdx.x * (THREADS / 32) + wid;   // global warp id

    // Prefetch the warp's FIRST dynamic grab now — its latency hides behind
    // the entire static phase.
    int next_base;
    if (lane == 0) {
        next_base = SROWS + atomicAdd(&g_ctr, RPG);
    }

    // ── Static bulk: 19 contiguous rows per warp, no atomics ──
    const int srow0 = wg * SRPW;
    #pragma unroll 1
    for (int rr = 0; rr < SRPW; rr++) {
        process_row(in, out, w4, lane, srow0 + rr);
    }

    // ── Dynamic tail: chunk=4, next grab prefetched before current chunk ──
    for (;;) {
        int base = __shfl_sync(0xffffffffu, next_base, 0);
        if (base >= ROWS) break;
        if (lane == 0) {
            next_base = SROWS + atomicAdd(&g_ctr, RPG);
        }
        #pragma unroll
        for (int rr = 0; rr < RPG; rr++) {
            process_row(in, out, w4, lane, base + rr);
        }
    }

    // ── Self-reset for graph replay: last block to finish zeroes counters ──
    __syncthreads();
    if (t == 0) {
        int old = atomicAdd(&g_done, 1);
        if (old == GRID - 1) {
            g_ctr  = 0;
            g_done = 0;
        }
    }
}

extern "C" void kernel_launch(void* const* d_in, const int* in_sizes, int n_in,
                              void* d_out, int out_size) {
    const float* in  = (const float*)d_in[0];
    float*       out = (float*)d_out;
    fractal_dim_kernel<<<GRID, THREADS>>>(in, out);
}

// round 8
// speedup vs baseline: 1.1563x; 1.1090x over previous
#include <cuda_runtime.h>

// out[row] = sum_l in[row*1024 + l] / (l+1),  rows = 131072, L = 1024.
//
// R8: R5's proven static schedule (one resident wave, balanced contiguous
// per-warp row ranges, smem weights, __ldcs, 8 front-batched float4/row)
// + paired-row reduction: rows processed two at a time, reduced with 6
// shuffles (2x cross-half exchange + shared 4-step butterfly) instead of
// 2x5. Lane 0 writes row A, lane 16 writes row B.
// Dynamic queues (R6/R7) regressed and are abandoned.

static constexpr int L       = 1024;
static constexpr int ROWS    = 4 * 8 * 4096;   // 131072
static constexpr int THREADS = 256;            // 8 warps
static constexpr int GRID    = 152 * 5;        // one full wave at 5 blocks/SM

__device__ __forceinline__ float row_partial(const float* __restrict__ in,
                                             const float4* __restrict__ w4,
                                             int lane, int row) {
    const float4* p = reinterpret_cast<const float4*>(in + (size_t)row * L) + lane;

    // Front-batch 8 loads (MLP=8 per warp), read-once streaming.
    float4 v[8];
    #pragma unroll
    for (int k = 0; k < 8; k++) {
        v[k] = __ldcs(p + k * 32);   // warp stride = 32 float4 = 128 floats
    }

    float s0 = 0.0f, s1 = 0.0f;
    #pragma unroll
    for (int k = 0; k < 8; k++) {
        float4 w = w4[lane + 32 * k];
        s0 = fmaf(v[k].x, w.x, s0);
        s1 = fmaf(v[k].y, w.y, s1);
        s0 = fmaf(v[k].z, w.z, s0);
        s1 = fmaf(v[k].w, w.w, s1);
    }
    return s0 + s1;
}

__global__ __launch_bounds__(THREADS, 5)
void fractal_dim_kernel(const float* __restrict__ in, float* __restrict__ out) {
    __shared__ float4 w4[L / 4];   // w4[i] = {1/(4i+1), ..., 1/(4i+4)}

    const int t = threadIdx.x;
    {
        int base = t * 4;
        float4 w;
        w.x = 1.0f / (float)(base + 1);
        w.y = 1.0f / (float)(base + 2);
        w.z = 1.0f / (float)(base + 3);
        w.w = 1.0f / (float)(base + 4);
        w4[t] = w;
    }
    __syncthreads();

    const int lane = t & 31;
    const int wid  = t >> 5;

    // Balanced contiguous split: block range, then warp range within it.
    const int bstart = (int)((long long)blockIdx.x       * ROWS / GRID);
    const int bend   = (int)((long long)(blockIdx.x + 1) * ROWS / GRID);
    const int n      = bend - bstart;
    const int wstart = bstart + (int)((long long)wid       * n / 8);
    const int wend   = bstart + (int)((long long)(wid + 1) * n / 8);

    int row = wstart;

    // ── Paired rows: 6-shuffle joint reduction ──
    for (; row + 1 < wend; row += 2) {
        float sA = row_partial(in, w4, lane, row);
        float sB = row_partial(in, w4, lane, row + 1);

        // Cross-half exchange, then select A into lanes 0-15, B into 16-31.
        float xa = sA + __shfl_xor_sync(0xffffffffu, sA, 16);
        float xb = sB + __shfl_xor_sync(0xffffffffu, sB, 16);
        float z  = (lane < 16) ? xa : xb;

        #pragma unroll
        for (int off = 8; off > 0; off >>= 1) {
            z += __shfl_xor_sync(0xffffffffu, z, off);
        }

        if (lane == 0)  out[row]     = z;   // full sum of row A
        if (lane == 16) out[row + 1] = z;   // full sum of row B
    }

    // ── Possible odd final row ──
    if (row < wend) {
        float s = row_partial(in, w4, lane, row);
        #pragma unroll
        for (int off = 16; off > 0; off >>= 1) {
            s += __shfl_xor_sync(0xffffffffu, s, off);
        }
        if (lane == 0) out[row] = s;
    }
}

extern "C" void kernel_launch(void* const* d_in, const int* in_sizes, int n_in,
                              void* d_out, int out_size) {
    const float* in  = (const float*)d_in[0];
    float*       out = (float*)d_out;
    fractal_dim_kernel<<<GRID, THREADS>>>(in, out);
}